// round 13
// baseline (speedup 1.0000x reference)
#include <cuda_runtime.h>
#include <cuda_fp16.h>
#include <cstdint>

#define NG 32
#define SV_P 65
#define RED_P 18

// A fragments fp16: [c(8)][mt(1024)][kt(16)][lane(32)] uint4 {a0,a1,a2,a3}
__device__ uint4 g_Af[8 * 1024 * 16 * 32];
// B fragments fp16, n8-tile PAIRS: [g(32)][kt(16)][ntp(16)][lane(32)] uint4
__device__ uint4 g_Bf[NG * 16 * 16 * 32];

// ---- smem map (bytes) ----
#define OFF_BIAS 0          // 1024
#define OFF_SV   1024       // 128*65*4 = 33280
#define OFF_RED  34304      // 4*128*18*4 = 36864 (also v0's sTe scratch)
#define OFF_SA   71168      // 3 x 16384 = 49152
#define OFF_SB   120320     // 3 x 32768 = 98304
#define SMEM_SZ  218624

__device__ __forceinline__ uint32_t s2u(const void* p) {
    uint32_t a;
    asm("{ .reg .u64 t; cvta.to.shared.u64 t, %1; cvt.u32.u64 %0, t; }" : "=r"(a) : "l"(p));
    return a;
}
__device__ __forceinline__ uint32_t pack_h2(float x, float y) {
    __half2 h = __floats2half2_rn(x, y);
    return *(uint32_t*)&h;
}
__device__ __forceinline__ void mma_f16(float* c, const uint32_t* a, uint32_t b0, uint32_t b1) {
    asm volatile(
        "mma.sync.aligned.m16n8k16.row.col.f32.f16.f16.f32 "
        "{%0,%1,%2,%3}, {%4,%5,%6,%7}, {%8,%9}, {%0,%1,%2,%3};"
        : "+f"(c[0]), "+f"(c[1]), "+f"(c[2]), "+f"(c[3])
        : "r"(a[0]), "r"(a[1]), "r"(a[2]), "r"(a[3]), "r"(b0), "r"(b1));
}
__device__ __forceinline__ void cpa16(uint32_t dst, const void* src) {
    asm volatile("cp.async.cg.shared.global [%0], [%1], 16;" :: "r"(dst), "l"(src) : "memory");
}
#define CP_COMMIT() asm volatile("cp.async.commit_group;" ::: "memory")
#define CP_WAIT1()  asm volatile("cp.async.wait_group 1;" ::: "memory")

// ---------------- fused prep: A blocks [0,8192), B blocks [8192,8704) ----------------
__global__ __launch_bounds__(256) void prep_AB(const float* __restrict__ nh,
                                               const float* __restrict__ U) {
    const int blk = blockIdx.x;
    if (blk < 8192) {                        // ---- A: c(8) x mt(1024) ----
        const int c = blk >> 10, mt = blk & 1023;
        #pragma unroll
        for (int s = 0; s < 2; s++) {
            int u = threadIdx.x + s * 256;   // kt(16) x lane(32)
            int kt = u >> 5, l = u & 31;
            int row = mt * 16 + (l >> 2);
            int k = kt * 16 + (l & 3) * 2;
            const float* p = nh + ((size_t)row * 8 + c) * 256 + k;
            float2 x0 = __ldg((const float2*)p);
            float2 x1 = __ldg((const float2*)(p + 8 * 2048));
            float2 x2 = __ldg((const float2*)(p + 8));
            float2 x3 = __ldg((const float2*)(p + 8 * 2048 + 8));
            size_t o = ((size_t)(c * 1024 + mt) * 16 + kt) * 32 + l;
            g_Af[o] = make_uint4(pack_h2(x0.x, x0.y), pack_h2(x1.x, x1.y),
                                 pack_h2(x2.x, x2.y), pack_h2(x3.x, x3.y));
        }
    } else {                                 // ---- B: g(32) x kt(16) ----
        const int bb = blk - 8192;
        const int g = bb >> 4, kt = bb & 15;
        const float* Ug = U + (size_t)g * 256 * 272;
        #pragma unroll
        for (int s = 0; s < 2; s++) {
            int u = threadIdx.x + s * 256;   // ntp(16) x lane(32)
            int ntp = u >> 5, l = u & 31;
            int k0 = kt * 16 + (l & 3) * 2;
            int nA = ntp * 16 + (l >> 2), nB = nA + 8;
            float a0 = __ldg(Ug + (size_t)k0 * 272 + nA);
            float a1 = __ldg(Ug + (size_t)(k0 + 1) * 272 + nA);
            float a8 = __ldg(Ug + (size_t)(k0 + 8) * 272 + nA);
            float a9 = __ldg(Ug + (size_t)(k0 + 9) * 272 + nA);
            float c0 = __ldg(Ug + (size_t)k0 * 272 + nB);
            float c1 = __ldg(Ug + (size_t)(k0 + 1) * 272 + nB);
            float c8 = __ldg(Ug + (size_t)(k0 + 8) * 272 + nB);
            float c9 = __ldg(Ug + (size_t)(k0 + 9) * 272 + nB);
            g_Bf[((size_t)(g * 16 + kt) * 16 + ntp) * 32 + l] =
                make_uint4(pack_h2(a0, a1), pack_h2(a8, a9),
                           pack_h2(c0, c1), pack_h2(c8, c9));
        }
    }
}

// ---- main: 128 CTAs x 512 threads (16 warps: mw4 x nwp4, tile 32x64), KC=64, N=256 ----
__global__ __launch_bounds__(512, 1)
void tt_main(const float* __restrict__ te, const float* __restrict__ bB,
             const float* __restrict__ Ut, const float* __restrict__ bt,
             const float* __restrict__ Uo, const float* __restrict__ bo,
             float* __restrict__ out)
{
    extern __shared__ __align__(16) char smem[];
    const uint32_t sbase = s2u(smem);
    float* sBias = (float*)(smem + OFF_BIAS);
    float* sV    = (float*)(smem + OFF_SV);
    float* red   = (float*)(smem + OFF_RED);

    const int tid = threadIdx.x;
    const int l   = tid & 31, w = tid >> 5;
    const int mw  = w >> 2,  nwp = w & 3;       // warp grid 4M x 4N (tile 32x64)
    const int b0  = blockIdx.x * 128;
    const int mt0 = blockIdx.x * 8;

    // ================= v0 = te @ U_type + b_type =================
    {
        float* sUt = (float*)(smem + OFF_SA);   // 4096 floats
        float* sTe = red;                       // 128x64, float4-rotated (32 KB)
        #pragma unroll
        for (int i = 0; i < 2; i++) {
            int idx = tid + i * 512;
            ((float4*)sUt)[idx] = __ldg((const float4*)Ut + idx);
        }
        #pragma unroll
        for (int i = 0; i < 4; i++) {
            int u = tid + i * 512;              // 2048 float4 units
            int m = u >> 4, t4 = u & 15;
            *(float4*)(sTe + m * 64 + ((t4 + m) & 15) * 4) =
                __ldg((const float4*)(te + (size_t)(b0 + m) * 64) + t4);
        }
        __syncthreads();
        const int m = tid & 127, aa = tid >> 7;
        float4 q0 = __ldg((const float4*)(bt + aa * 16) + 0);
        float4 q1 = __ldg((const float4*)(bt + aa * 16) + 1);
        float4 q2 = __ldg((const float4*)(bt + aa * 16) + 2);
        float4 q3 = __ldg((const float4*)(bt + aa * 16) + 3);
        float vv[16] = {q0.x,q0.y,q0.z,q0.w, q1.x,q1.y,q1.z,q1.w,
                        q2.x,q2.y,q2.z,q2.w, q3.x,q3.y,q3.z,q3.w};
        #pragma unroll 4
        for (int t4 = 0; t4 < 16; t4++) {
            float4 xv = *(float4*)(sTe + m * 64 + ((t4 + m) & 15) * 4);
            float xs[4] = {xv.x, xv.y, xv.z, xv.w};
            #pragma unroll
            for (int e = 0; e < 4; e++) {
                float x = xs[e];
                const float4* ur = (const float4*)(sUt + aa * 1024 + (t4 * 4 + e) * 16);
                float4 u0 = ur[0], u1 = ur[1], u2 = ur[2], u3 = ur[3];
                vv[0]+=x*u0.x; vv[1]+=x*u0.y; vv[2]+=x*u0.z; vv[3]+=x*u0.w;
                vv[4]+=x*u1.x; vv[5]+=x*u1.y; vv[6]+=x*u1.z; vv[7]+=x*u1.w;
                vv[8]+=x*u2.x; vv[9]+=x*u2.y; vv[10]+=x*u2.z; vv[11]+=x*u2.w;
                vv[12]+=x*u3.x; vv[13]+=x*u3.y; vv[14]+=x*u3.z; vv[15]+=x*u3.w;
            }
        }
        #pragma unroll
        for (int j = 0; j < 16; j++) sV[m * SV_P + aa * 16 + j] = vv[j];
        __syncthreads();
    }

    // ===== pipeline: 128 chunks = g(32) x kc(4), KC=64, N=256, 3-stage cp.async =====
    auto issue = [&](int q, int buf) {
        const int g = q >> 2, kc = q & 3;
        const int c = g >> 2;
        const uint32_t aDst = sbase + OFF_SA + buf * 16384;
        #pragma unroll
        for (int s = 0; s < 2; s++) {
            int u = tid + s * 512;              // 1024: mtL(8) x ktL(4) x l(32)
            int mtL = u >> 7, ktL = (u >> 5) & 3, ll = u & 31;
            size_t o = ((size_t)(c * 1024 + mt0 + mtL) * 16 + kc * 4 + ktL) * 32 + ll;
            cpa16(aDst + u * 16, g_Af + o);
        }
        const uint32_t bDst = sbase + OFF_SB + buf * 32768;
        #pragma unroll
        for (int s = 0; s < 4; s++) {
            int u = tid + s * 512;              // 2048: ktL(4) x ntp(16) x l(32)
            int ktL = u >> 9, ntp = (u >> 5) & 15, ll = u & 31;
            size_t o = ((size_t)(g * 16 + kc * 4 + ktL) * 16 + ntp) * 32 + ll;
            cpa16(bDst + u * 16, g_Bf + o);
        }
        CP_COMMIT();
    };

    auto reduce_g = [&](int aP) {
        int row = tid & 127, jq = tid >> 7;
        #pragma unroll
        for (int e = 0; e < 4; e++) {
            float s = red[(0 * 128 + row) * RED_P + jq * 4 + e]
                    + red[(1 * 128 + row) * RED_P + jq * 4 + e]
                    + red[(2 * 128 + row) * RED_P + jq * 4 + e]
                    + red[(3 * 128 + row) * RED_P + jq * 4 + e];
            sV[row * SV_P + aP * 16 + jq * 4 + e] = s;
        }
    };

    issue(0, 0);
    issue(1, 1);

    float acc[2][8][4];   // mt x nt(8 n8-tiles) x frag  (64 regs)
    int bufC = 0, bufN = 2;   // compute buf for q, issue buf for q+2 (mod 3 counters)

    #pragma unroll 1
    for (int q = 0; q < 128; q++) {
        const int g = q >> 2, kc = q & 3;
        const int a = g & 3;

        CP_WAIT1();                 // group q done; group q+1 may still be in flight
        __syncthreads();
        if (q + 2 < 128) issue(q + 2, bufN);

        if (kc == 1 && q >= 4) reduce_g((g - 1) & 3);

        if (kc == 0) {
            if (tid < 64)
                ((float4*)sBias)[tid] = __ldg((const float4*)(bB + (size_t)g * 272) + tid);
            #pragma unroll
            for (int mt = 0; mt < 2; mt++)
                #pragma unroll
                for (int nt = 0; nt < 8; nt++)
                    #pragma unroll
                    for (int e = 0; e < 4; e++) acc[mt][nt][e] = 0.f;
        }

        // ---- compute: 4 k16-steps x 8 n8-tiles ----
        const char* sAb = smem + OFF_SA + bufC * 16384;
        const char* sBb = smem + OFF_SB + bufC * 32768;
        #pragma unroll
        for (int ktL = 0; ktL < 4; ktL++) {
            uint32_t Ah[2][4];
            #pragma unroll
            for (int mt = 0; mt < 2; mt++)
                *(uint4*)Ah[mt] = *(const uint4*)(sAb +
                    (((mw * 2 + mt) * 4 + ktL) * 32 + l) * 16);
            uint4 Bp[4];
            #pragma unroll
            for (int np = 0; np < 4; np++)
                Bp[np] = *(const uint4*)(sBb +
                    ((ktL * 16 + nwp * 4 + np) * 32 + l) * 16);
            #pragma unroll
            for (int np = 0; np < 4; np++)
                #pragma unroll
                for (int mt = 0; mt < 2; mt++) {
                    mma_f16(acc[mt][np * 2],     Ah[mt], Bp[np].x, Bp[np].y);
                    mma_f16(acc[mt][np * 2 + 1], Ah[mt], Bp[np].z, Bp[np].w);
                }
        }

        // ---- epilogue: warp owns i = nwp*4..+4, all 16 i covered per g ----
        if (kc == 3) {
            const int j0 = (l & 3) * 2;
            #pragma unroll
            for (int p = 0; p < 4; p++) {
                int row = mw * 32 + (l >> 2) + p * 8;
                int mt = p >> 1, h = (p & 1) * 2;
                float2 pj = make_float2(0.f, 0.f), pk = make_float2(0.f, 0.f);
                #pragma unroll
                for (int np = 0; np < 4; np++) {
                    int i = nwp * 4 + np;
                    float coef = sV[row * SV_P + a * 16 + i] + ((i == 15) ? 1.f : 0.f);
                    float2 bj = *(float2*)(sBias + i * 16 + j0);
                    float2 bk = *(float2*)(sBias + i * 16 + j0 + 8);
                    pj.x += coef * (acc[mt][np * 2][h + 0] + bj.x);
                    pj.y += coef * (acc[mt][np * 2][h + 1] + bj.y);
                    pk.x += coef * (acc[mt][np * 2 + 1][h + 0] + bk.x);
                    pk.y += coef * (acc[mt][np * 2 + 1][h + 1] + bk.y);
                }
                *(float2*)(red + (nwp * 128 + row) * RED_P + j0)     = pj;
                *(float2*)(red + (nwp * 128 + row) * RED_P + j0 + 8) = pk;
            }
        }

        bufC = (bufC == 2) ? 0 : bufC + 1;
        bufN = (bufN == 2) ? 0 : bufN + 1;
    }

    __syncthreads();                // g=31 partials visible
    reduce_g(3);
    __syncthreads();

    // ================= output projection (single pass, a = tid>>7 in 0..3) ============
    {
        float* sUo = (float*)(smem + OFF_SA);           // 64 KB overlay (SA + SB head)
        float* sBo = (float*)(smem + OFF_SA + 65536);   // 1024 floats
        #pragma unroll
        for (int i = 0; i < 8; i++) {
            int idx = tid + i * 512;
            ((float4*)sUo)[idx] = __ldg((const float4*)Uo + idx);
        }
        if (tid < 256) ((float4*)sBo)[tid] = __ldg((const float4*)bo + tid);
        __syncthreads();
        const int a = tid >> 7, h2 = (tid & 127) * 2;
        float2 uo[16];
        #pragma unroll
        for (int r = 0; r < 16; r++)
            uo[r] = *(float2*)(sUo + (a * 16 + r) * 256 + h2);
        float2 b2 = *(float2*)(sBo + a * 256 + h2);
        #pragma unroll 2
        for (int m = 0; m < 128; m++) {
            float sx = b2.x, sy = b2.y;
            const float* vr = sV + m * SV_P + a * 16;
            #pragma unroll
            for (int r = 0; r < 16; r++) {
                float vvv = vr[r];
                sx += vvv * uo[r].x; sy += vvv * uo[r].y;
            }
            *(float2*)(out + (size_t)(b0 + m) * 1024 + a * 256 + h2) = make_float2(sx, sy);
        }
    }
}

extern "C" void kernel_launch(void* const* d_in, const int* in_sizes, int n_in,
                              void* d_out, int out_size) {
    const float* nh = (const float*)d_in[0];
    const float* te = (const float*)d_in[1];
    const float* U  = (const float*)d_in[2];
    const float* bB = (const float*)d_in[3];
    const float* Ut = (const float*)d_in[4];
    const float* bt = (const float*)d_in[5];
    const float* Uo = (const float*)d_in[6];
    const float* bo = (const float*)d_in[7];
    float* out = (float*)d_out;

    prep_AB<<<8704, 256>>>(nh, U);
    cudaFuncSetAttribute(tt_main, cudaFuncAttributeMaxDynamicSharedMemorySize, SMEM_SZ);
    tt_main<<<128, 512, SMEM_SZ>>>(te, bB, Ut, bt, Uo, bo, out);
}

// round 14
// speedup vs baseline: 1.0078x; 1.0078x over previous
#include <cuda_runtime.h>
#include <cuda_fp16.h>
#include <cstdint>

#define NG 32
#define SV_P 65
#define RED_P 18

// A fragments fp16: [c(8)][mt(1024)][kt(16)][lane(32)] uint4 {a0,a1,a2,a3}
__device__ uint4 g_Af[8 * 1024 * 16 * 32];
// B fragments fp16, n8-tile PAIRS: [g(32)][kt(16)][ntp(16)][lane(32)] uint4
__device__ uint4 g_Bf[NG * 16 * 16 * 32];

// ---- smem map (bytes) ----
#define OFF_BIAS 0          // 2 x 1024 (double-buffered by g parity)
#define OFF_SV   2048       // 128*65*4 = 33280
#define OFF_RED  35328      // 4*128*18*4 = 36864 (also v0's sTe scratch)
#define OFF_SA   72192      // 3 x 16384 = 49152
#define OFF_SB   121344     // 3 x 32768 = 98304
#define SMEM_SZ  219648

__device__ __forceinline__ uint32_t s2u(const void* p) {
    uint32_t a;
    asm("{ .reg .u64 t; cvta.to.shared.u64 t, %1; cvt.u32.u64 %0, t; }" : "=r"(a) : "l"(p));
    return a;
}
__device__ __forceinline__ uint32_t pack_h2(float x, float y) {
    __half2 h = __floats2half2_rn(x, y);
    return *(uint32_t*)&h;
}
__device__ __forceinline__ void mma_f16(float* c, const uint32_t* a, uint32_t b0, uint32_t b1) {
    asm volatile(
        "mma.sync.aligned.m16n8k16.row.col.f32.f16.f16.f32 "
        "{%0,%1,%2,%3}, {%4,%5,%6,%7}, {%8,%9}, {%0,%1,%2,%3};"
        : "+f"(c[0]), "+f"(c[1]), "+f"(c[2]), "+f"(c[3])
        : "r"(a[0]), "r"(a[1]), "r"(a[2]), "r"(a[3]), "r"(b0), "r"(b1));
}
__device__ __forceinline__ void cpa16(uint32_t dst, const void* src) {
    asm volatile("cp.async.cg.shared.global [%0], [%1], 16;" :: "r"(dst), "l"(src) : "memory");
}
#define CP_COMMIT() asm volatile("cp.async.commit_group;" ::: "memory")
#define CP_WAIT1()  asm volatile("cp.async.wait_group 1;" ::: "memory")

// ---------------- fused prep: A blocks [0,8192), B blocks [8192,8704) ----------------
__global__ __launch_bounds__(256) void prep_AB(const float* __restrict__ nh,
                                               const float* __restrict__ U) {
    const int blk = blockIdx.x;
    if (blk < 8192) {                        // ---- A: c(8) x mt(1024) ----
        const int c = blk >> 10, mt = blk & 1023;
        #pragma unroll
        for (int s = 0; s < 2; s++) {
            int u = threadIdx.x + s * 256;   // kt(16) x lane(32)
            int kt = u >> 5, l = u & 31;
            int row = mt * 16 + (l >> 2);
            int k = kt * 16 + (l & 3) * 2;
            const float* p = nh + ((size_t)row * 8 + c) * 256 + k;
            float2 x0 = __ldg((const float2*)p);
            float2 x1 = __ldg((const float2*)(p + 8 * 2048));
            float2 x2 = __ldg((const float2*)(p + 8));
            float2 x3 = __ldg((const float2*)(p + 8 * 2048 + 8));
            size_t o = ((size_t)(c * 1024 + mt) * 16 + kt) * 32 + l;
            g_Af[o] = make_uint4(pack_h2(x0.x, x0.y), pack_h2(x1.x, x1.y),
                                 pack_h2(x2.x, x2.y), pack_h2(x3.x, x3.y));
        }
    } else {                                 // ---- B: g(32) x kt(16) ----
        const int bb = blk - 8192;
        const int g = bb >> 4, kt = bb & 15;
        const float* Ug = U + (size_t)g * 256 * 272;
        #pragma unroll
        for (int s = 0; s < 2; s++) {
            int u = threadIdx.x + s * 256;   // ntp(16) x lane(32)
            int ntp = u >> 5, l = u & 31;
            int k0 = kt * 16 + (l & 3) * 2;
            int nA = ntp * 16 + (l >> 2), nB = nA + 8;
            float a0 = __ldg(Ug + (size_t)k0 * 272 + nA);
            float a1 = __ldg(Ug + (size_t)(k0 + 1) * 272 + nA);
            float a8 = __ldg(Ug + (size_t)(k0 + 8) * 272 + nA);
            float a9 = __ldg(Ug + (size_t)(k0 + 9) * 272 + nA);
            float c0 = __ldg(Ug + (size_t)k0 * 272 + nB);
            float c1 = __ldg(Ug + (size_t)(k0 + 1) * 272 + nB);
            float c8 = __ldg(Ug + (size_t)(k0 + 8) * 272 + nB);
            float c9 = __ldg(Ug + (size_t)(k0 + 9) * 272 + nB);
            g_Bf[((size_t)(g * 16 + kt) * 16 + ntp) * 32 + l] =
                make_uint4(pack_h2(a0, a1), pack_h2(a8, a9),
                           pack_h2(c0, c1), pack_h2(c8, c9));
        }
    }
}

// ---- main: 128 CTAs x 512 threads (16 warps: mw4 x nwp4, tile 32x64), KC=64, N=256 ----
__global__ __launch_bounds__(512, 1)
void tt_main(const float* __restrict__ te, const float* __restrict__ bB,
             const float* __restrict__ Ut, const float* __restrict__ bt,
             const float* __restrict__ Uo, const float* __restrict__ bo,
             float* __restrict__ out)
{
    extern __shared__ __align__(16) char smem[];
    const uint32_t sbase = s2u(smem);
    float* sBias = (float*)(smem + OFF_BIAS);
    float* sV    = (float*)(smem + OFF_SV);
    float* red   = (float*)(smem + OFF_RED);

    const int tid = threadIdx.x;
    const int l   = tid & 31, w = tid >> 5;
    const int mw  = w >> 2,  nwp = w & 3;       // warp grid 4M x 4N (tile 32x64)
    const int b0  = blockIdx.x * 128;
    const int mt0 = blockIdx.x * 8;

    // thread-constant cp.async offsets (element indices into g_Af / g_Bf)
    int aOff[2], bOff[4];
    #pragma unroll
    for (int s = 0; s < 2; s++) {
        int u = tid + s * 512;                  // mtL(8) x ktL(4) x l(32)
        aOff[s] = (mt0 + (u >> 7)) * 512 + ((u >> 5) & 3) * 32 + (u & 31);
    }
    #pragma unroll
    for (int s = 0; s < 4; s++) {
        int u = tid + s * 512;                  // ktL(4) x ntp(16) x l(32)
        bOff[s] = (u >> 9) * 512 + ((u >> 5) & 15) * 32 + (u & 31);
    }

    // ================= v0 = te @ U_type + b_type =================
    {
        float* sUt = (float*)(smem + OFF_SA);   // 4096 floats
        float* sTe = red;                       // 128x64, float4-rotated (32 KB)
        #pragma unroll
        for (int i = 0; i < 2; i++) {
            int idx = tid + i * 512;
            ((float4*)sUt)[idx] = __ldg((const float4*)Ut + idx);
        }
        #pragma unroll
        for (int i = 0; i < 4; i++) {
            int u = tid + i * 512;              // 2048 float4 units
            int m = u >> 4, t4 = u & 15;
            *(float4*)(sTe + m * 64 + ((t4 + m) & 15) * 4) =
                __ldg((const float4*)(te + (size_t)(b0 + m) * 64) + t4);
        }
        __syncthreads();
        const int m = tid & 127, aa = tid >> 7;
        float4 q0 = __ldg((const float4*)(bt + aa * 16) + 0);
        float4 q1 = __ldg((const float4*)(bt + aa * 16) + 1);
        float4 q2 = __ldg((const float4*)(bt + aa * 16) + 2);
        float4 q3 = __ldg((const float4*)(bt + aa * 16) + 3);
        float vv[16] = {q0.x,q0.y,q0.z,q0.w, q1.x,q1.y,q1.z,q1.w,
                        q2.x,q2.y,q2.z,q2.w, q3.x,q3.y,q3.z,q3.w};
        #pragma unroll 4
        for (int t4 = 0; t4 < 16; t4++) {
            float4 xv = *(float4*)(sTe + m * 64 + ((t4 + m) & 15) * 4);
            float xs[4] = {xv.x, xv.y, xv.z, xv.w};
            #pragma unroll
            for (int e = 0; e < 4; e++) {
                float x = xs[e];
                const float4* ur = (const float4*)(sUt + aa * 1024 + (t4 * 4 + e) * 16);
                float4 u0 = ur[0], u1 = ur[1], u2 = ur[2], u3 = ur[3];
                vv[0]+=x*u0.x; vv[1]+=x*u0.y; vv[2]+=x*u0.z; vv[3]+=x*u0.w;
                vv[4]+=x*u1.x; vv[5]+=x*u1.y; vv[6]+=x*u1.z; vv[7]+=x*u1.w;
                vv[8]+=x*u2.x; vv[9]+=x*u2.y; vv[10]+=x*u2.z; vv[11]+=x*u2.w;
                vv[12]+=x*u3.x; vv[13]+=x*u3.y; vv[14]+=x*u3.z; vv[15]+=x*u3.w;
            }
        }
        #pragma unroll
        for (int j = 0; j < 16; j++) sV[m * SV_P + aa * 16 + j] = vv[j];
        __syncthreads();
    }

    // ===== pipeline: 128 chunks = g(32) x kc(4), KC=64, N=256, 3-stage cp.async =====
    auto issue = [&](int q2, int buf) {
        const int g = q2 >> 2, kc = q2 & 3;
        const int c = g >> 2;
        const uint32_t aDst = sbase + OFF_SA + buf * 16384;
        #pragma unroll
        for (int s = 0; s < 2; s++)
            cpa16(aDst + (tid + s * 512) * 16,
                  g_Af + (c * 524288 + kc * 128 + aOff[s]));
        const uint32_t bDst = sbase + OFF_SB + buf * 32768;
        #pragma unroll
        for (int s = 0; s < 4; s++)
            cpa16(bDst + (tid + s * 512) * 16,
                  g_Bf + (g * 8192 + kc * 2048 + bOff[s]));
        if (kc == 0 && tid < 64)   // bias for group g rides with its first chunk
            cpa16(sbase + OFF_BIAS + (g & 1) * 1024 + tid * 16,
                  bB + (size_t)g * 272 + tid * 4);
        CP_COMMIT();
    };

    auto reduce_g = [&](int aP) {
        int row = tid & 127, jq = tid >> 7;
        #pragma unroll
        for (int e = 0; e < 4; e++) {
            float s = red[(0 * 128 + row) * RED_P + jq * 4 + e]
                    + red[(1 * 128 + row) * RED_P + jq * 4 + e]
                    + red[(2 * 128 + row) * RED_P + jq * 4 + e]
                    + red[(3 * 128 + row) * RED_P + jq * 4 + e];
            sV[row * SV_P + aP * 16 + jq * 4 + e] = s;
        }
    };

    issue(0, 0);
    issue(1, 1);

    float acc[2][8][4];   // mt x nt(8 n8-tiles) x frag  (64 regs)
    int bufC = 0, bufN = 2;

    #pragma unroll 1
    for (int q = 0; q < 128; q++) {
        const int g = q >> 2, kc = q & 3;
        const int a = g & 3;

        CP_WAIT1();                 // group q done; group q+1 may still be in flight
        __syncthreads();
        if (q + 2 < 128) issue(q + 2, bufN);

        if (kc == 1 && q >= 4) reduce_g((g - 1) & 3);

        if (kc == 0) {
            #pragma unroll
            for (int mt = 0; mt < 2; mt++)
                #pragma unroll
                for (int nt = 0; nt < 8; nt++)
                    #pragma unroll
                    for (int e = 0; e < 4; e++) acc[mt][nt][e] = 0.f;
        }

        // ---- compute: 4 k16-steps x 8 n8-tiles ----
        const char* sAb = smem + OFF_SA + bufC * 16384;
        const char* sBb = smem + OFF_SB + bufC * 32768;
        #pragma unroll
        for (int ktL = 0; ktL < 4; ktL++) {
            uint32_t Ah[2][4];
            #pragma unroll
            for (int mt = 0; mt < 2; mt++)
                *(uint4*)Ah[mt] = *(const uint4*)(sAb +
                    (((mw * 2 + mt) * 4 + ktL) * 32 + l) * 16);
            uint4 Bp[4];
            #pragma unroll
            for (int np = 0; np < 4; np++)
                Bp[np] = *(const uint4*)(sBb +
                    ((ktL * 16 + nwp * 4 + np) * 32 + l) * 16);
            #pragma unroll
            for (int np = 0; np < 4; np++)
                #pragma unroll
                for (int mt = 0; mt < 2; mt++) {
                    mma_f16(acc[mt][np * 2],     Ah[mt], Bp[np].x, Bp[np].y);
                    mma_f16(acc[mt][np * 2 + 1], Ah[mt], Bp[np].z, Bp[np].w);
                }
        }

        // ---- epilogue: warp owns i = nwp*4..+4, all 16 i covered per g ----
        if (kc == 3) {
            const float* bias = sBias + (g & 1) * 256;
            const int j0 = (l & 3) * 2;
            #pragma unroll
            for (int p = 0; p < 4; p++) {
                int row = mw * 32 + (l >> 2) + p * 8;
                int mt = p >> 1, h = (p & 1) * 2;
                float2 pj = make_float2(0.f, 0.f), pk = make_float2(0.f, 0.f);
                #pragma unroll
                for (int np = 0; np < 4; np++) {
                    int i = nwp * 4 + np;
                    float coef = sV[row * SV_P + a * 16 + i] + ((i == 15) ? 1.f : 0.f);
                    float2 bj = *(float2*)(bias + i * 16 + j0);
                    float2 bk = *(float2*)(bias + i * 16 + j0 + 8);
                    pj.x += coef * (acc[mt][np * 2][h + 0] + bj.x);
                    pj.y += coef * (acc[mt][np * 2][h + 1] + bj.y);
                    pk.x += coef * (acc[mt][np * 2 + 1][h + 0] + bk.x);
                    pk.y += coef * (acc[mt][np * 2 + 1][h + 1] + bk.y);
                }
                *(float2*)(red + (nwp * 128 + row) * RED_P + j0)     = pj;
                *(float2*)(red + (nwp * 128 + row) * RED_P + j0 + 8) = pk;
            }
        }

        bufC = (bufC == 2) ? 0 : bufC + 1;
        bufN = (bufN == 2) ? 0 : bufN + 1;
    }

    __syncthreads();                // g=31 partials visible
    reduce_g(3);
    __syncthreads();

    // ================= output projection (single pass, a = tid>>7 in 0..3) ============
    {
        float* sUo = (float*)(smem + OFF_SA);           // 64 KB overlay (SA + SB head)
        float* sBo = (float*)(smem + OFF_SA + 65536);   // 1024 floats
        #pragma unroll
        for (int i = 0; i < 8; i++) {
            int idx = tid + i * 512;
            ((float4*)sUo)[idx] = __ldg((const float4*)Uo + idx);
        }
        if (tid < 256) ((float4*)sBo)[tid] = __ldg((const float4*)bo + tid);
        __syncthreads();
        const int a = tid >> 7, h2 = (tid & 127) * 2;
        float2 uo[16];
        #pragma unroll
        for (int r = 0; r < 16; r++)
            uo[r] = *(float2*)(sUo + (a * 16 + r) * 256 + h2);
        float2 b2 = *(float2*)(sBo + a * 256 + h2);
        #pragma unroll 2
        for (int m = 0; m < 128; m++) {
            float sx = b2.x, sy = b2.y;
            const float* vr = sV + m * SV_P + a * 16;
            #pragma unroll
            for (int r = 0; r < 16; r++) {
                float vvv = vr[r];
                sx += vvv * uo[r].x; sy += vvv * uo[r].y;
            }
            *(float2*)(out + (size_t)(b0 + m) * 1024 + a * 256 + h2) = make_float2(sx, sy);
        }
    }
}

extern "C" void kernel_launch(void* const* d_in, const int* in_sizes, int n_in,
                              void* d_out, int out_size) {
    const float* nh = (const float*)d_in[0];
    const float* te = (const float*)d_in[1];
    const float* U  = (const float*)d_in[2];
    const float* bB = (const float*)d_in[3];
    const float* Ut = (const float*)d_in[4];
    const float* bt = (const float*)d_in[5];
    const float* Uo = (const float*)d_in[6];
    const float* bo = (const float*)d_in[7];
    float* out = (float*)d_out;

    prep_AB<<<8704, 256>>>(nh, U);
    cudaFuncSetAttribute(tt_main, cudaFuncAttributeMaxDynamicSharedMemorySize, SMEM_SZ);
    tt_main<<<128, 512, SMEM_SZ>>>(te, bB, Ut, bt, Uo, bo, out);
}